// round 14
// baseline (speedup 1.0000x reference)
#include <cuda_runtime.h>
#include <cuda_fp16.h>
#include <math.h>

#define NN 100000
#define EE 1600000
#define DIN 384
#define HDIM 128
#define HHALF 64
#define NLAYERS 3
#define NRL 4
#define EPSBN 1e-5f

#define SCAN_NB 200
#define SCAN_CHUNK 500

#define MIDC 192   // concatenated heads hidden width

// ---------------- scratch (device globals; no allocation allowed) ------------
__device__ float   g_h[NN * HDIM];       // current node features (tf32-rounded)
__device__ __half2 g_hw2[NN * HDIM / 2]; // (h @ Wc[i]) * dinv[row], fp16
__device__ float   g_mid[NN * MIDC];     // heads hidden
__device__ float   g_w1cat[HDIM * MIDC];
__device__ float   g_b1cat[MIDC];
__device__ float   g_wp_r[DIN * HDIM];            // tf32-rounded Wp
__device__ float   g_wc_r[NLAYERS * HDIM * HDIM]; // tf32-rounded Wc
__device__ float   g_dinv[NN];
__device__ int     g_cnt[NN];
__device__ int     g_rowptr[NN + 1];
__device__ int     g_csr_src[EE];
__device__ int     g_bsum[SCAN_NB];
__device__ int     g_boff[SCAN_NB];

__device__ __forceinline__ unsigned f2tf32(float x) {
    unsigned r;
    asm("cvt.rna.tf32.f32 %0, %1;" : "=r"(r) : "f"(x));
    return r;
}
__device__ __forceinline__ float tf32round(float x) {
    return __uint_as_float(f2tf32(x));
}

// ---------------- weight prep: tf32 pre-rounding -----------------------------
__global__ void round_weights_kernel(const float* __restrict__ Wp,
                                     const float* __restrict__ Wc) {
    int idx = blockIdx.x * blockDim.x + threadIdx.x;
    if (idx >= DIN * HDIM) return;
    g_wp_r[idx] = tf32round(Wp[idx]);
    g_wc_r[idx] = tf32round(Wc[idx]);
}

// ---------------- heads weight concat (tf32-rounded) --------------------------
__global__ void w1cat_kernel(const float* __restrict__ rs_W1, const float* __restrict__ rs_b1,
                             const float* __restrict__ rl_W1, const float* __restrict__ rl_b1,
                             const float* __restrict__ rel_W1, const float* __restrict__ rel_b1) {
    int idx = blockIdx.x * blockDim.x + threadIdx.x;   // [0, 128*192)
    if (idx >= HDIM * MIDC) return;
    int k = idx / MIDC, c = idx % MIDC;
    int head = c >> 6, j = c & 63;
    const float* W1 = (head == 0) ? rs_W1 : (head == 1) ? rl_W1 : rel_W1;
    g_w1cat[idx] = tf32round(W1[k * HHALF + j]);
    if (k == 0) {
        const float* B1 = (head == 0) ? rs_b1 : (head == 1) ? rl_b1 : rel_b1;
        g_b1cat[c] = B1[j];
    }
}

// ---------------- degree count ------------------------------------------------
__global__ void deg_init_kernel() {
    int i = blockIdx.x * blockDim.x + threadIdx.x;
    if (i < NN) g_cnt[i] = 0;
}

__global__ void deg_count_kernel(const int* __restrict__ ei) {
    int e = blockIdx.x * blockDim.x + threadIdx.x;
    if (e < EE) atomicAdd(&g_cnt[ei[EE + e]], 1);
}

// ---------------- 3-phase parallel scan --------------------------------------
__global__ void scan_partial_kernel() {   // grid SCAN_NB, block 512
    __shared__ int sh[512];
    int b = blockIdx.x, t = threadIdx.x;
    int i = b * SCAN_CHUNK + t;
    sh[t] = (t < SCAN_CHUNK) ? g_cnt[i] : 0;
    __syncthreads();
#pragma unroll
    for (int o = 256; o; o >>= 1) {
        if (t < o) sh[t] += sh[t + o];
        __syncthreads();
    }
    if (t == 0) g_bsum[b] = sh[0];
}

__global__ void scan_bsum_kernel() {      // 1 block, 256 threads
    __shared__ int sh[256];
    int t = threadIdx.x;
    sh[t] = (t < SCAN_NB) ? g_bsum[t] : 0;
    __syncthreads();
#pragma unroll
    for (int o = 1; o < 256; o <<= 1) {
        int v = (t >= o) ? sh[t - o] : 0;
        __syncthreads();
        sh[t] += v;
        __syncthreads();
    }
    if (t < SCAN_NB) g_boff[t] = (t ? sh[t - 1] : 0);
    if (t == 0) g_rowptr[NN] = EE;
}

__global__ void scan_fill_kernel() {      // grid SCAN_NB, block 512
    __shared__ int sh[512];
    int b = blockIdx.x, t = threadIdx.x;
    int i = b * SCAN_CHUNK + t;
    int c = (t < SCAN_CHUNK) ? g_cnt[i] : 0;
    sh[t] = c;
    __syncthreads();
#pragma unroll
    for (int o = 1; o < 512; o <<= 1) {
        int v = (t >= o) ? sh[t - o] : 0;
        __syncthreads();
        sh[t] += v;
        __syncthreads();
    }
    if (t < SCAN_CHUNK) {
        g_rowptr[i] = g_boff[b] + sh[t] - c;    // exclusive
        g_cnt[i] = 0;
        g_dinv[i] = rsqrtf((float)(c + 1));     // deg = in-degree + self loop
    }
}

__global__ void csr_fill_kernel(const int* __restrict__ ei) {
    int e = blockIdx.x * blockDim.x + threadIdx.x;
    if (e >= EE) return;
    int src = ei[e];
    int dst = ei[EE + e];
    int pos = g_rowptr[dst] + atomicAdd(&g_cnt[dst], 1);
    g_csr_src[pos] = src;
}

// ---------------- tf32 tensor-core GEMM v5 (multi-stage cp.async) -------------
__device__ __forceinline__ void mma_tf32(float* c, const unsigned* a, const unsigned* b) {
    asm volatile(
        "mma.sync.aligned.m16n8k8.row.col.f32.tf32.tf32.f32 "
        "{%0,%1,%2,%3}, {%4,%5,%6,%7}, {%8,%9}, {%0,%1,%2,%3};"
        : "+f"(c[0]), "+f"(c[1]), "+f"(c[2]), "+f"(c[3])
        : "r"(a[0]), "r"(a[1]), "r"(a[2]), "r"(a[3]), "r"(b[0]), "r"(b[1]));
}

__device__ __forceinline__ void cp_async16(float* sdst, const float* gsrc, bool valid) {
    unsigned saddr = (unsigned)__cvta_generic_to_shared(sdst);
    int sz = valid ? 16 : 0;
    asm volatile("cp.async.cg.shared.global [%0], [%1], 16, %2;"
                 :: "r"(saddr), "l"(gsrc), "r"(sz));
}
__device__ __forceinline__ void cp_commit() { asm volatile("cp.async.commit_group;"); }
template <int N> __device__ __forceinline__ void cp_wait() {
    asm volatile("cp.async.wait_group %0;" :: "n"(N));
}

// C[M,NCOLS] = A[M,K] @ W[K,NCOLS] (+bias)(+relu)(*dinv[row]) -> f32/tf32/half2
// BM=128, BK=16. WM x WN warps; warp tile (128/WM) x (NCOLS/WN). NSTAGE-deep pipeline.
#define ASTRIDE 20
template <int K, int NCOLS, int WM, int WN, int NSTAGE,
          bool ACVT, bool RELU, bool BIAS, bool SCALE, int OUTMODE>  // 0=f32,1=tf32,2=half2
__device__ __forceinline__ void gemm_tf32_body(const float* __restrict__ A,
                                               const float* __restrict__ W,
                                               const float* __restrict__ bias,
                                               void* __restrict__ Cv) {
    constexpr int THREADS = WM * WN * 32;
    constexpr int MT = 128 / (16 * WM);
    constexpr int NT = NCOLS / (8 * WN);
    constexpr int BSTRIDE = NCOLS + 8;
    constexpr int NK = K / 16;
    constexpr int SA = 128 * ASTRIDE;     // floats per A stage
    constexpr int SB = 16 * BSTRIDE;      // floats per B stage
    constexpr int SS = SA + SB;

    extern __shared__ float sm[];

    const int tid = threadIdx.x;
    const int wid = tid >> 5, lane = tid & 31;
    const int wm = wid % WM, wn = wid / WM;
    const int g = lane >> 2, t = lane & 3;
    const int m0 = blockIdx.x * 128;

    float acc[MT][NT][4];
#pragma unroll
    for (int mt = 0; mt < MT; mt++)
#pragma unroll
        for (int nt = 0; nt < NT; nt++)
#pragma unroll
            for (int i = 0; i < 4; i++) acc[mt][nt][i] = 0.0f;

    auto load_tiles = [&](int s, int k0) {
        float* As = sm + s * SS;
        float* Bs = As + SA;
#pragma unroll
        for (int idx = tid; idx < 512; idx += THREADS) {   // A: 128x16 = 512 float4
            int r = idx >> 2, c4 = (idx & 3) * 4;
            int gr = m0 + r;
            bool v = (gr < NN);
            const float* src = A + (size_t)(v ? gr : 0) * K + k0 + c4;
            cp_async16(&As[r * ASTRIDE + c4], src, v);
        }
#pragma unroll
        for (int idx = tid; idx < 4 * NCOLS; idx += THREADS) {  // B: 16xNCOLS
            int kr = idx / (NCOLS / 4), c4 = (idx % (NCOLS / 4)) * 4;
            cp_async16(&Bs[kr * BSTRIDE + c4], W + (size_t)(k0 + kr) * NCOLS + c4, true);
        }
        cp_commit();
    };

#pragma unroll
    for (int p = 0; p < NSTAGE - 1; p++) load_tiles(p, p * 16);

    for (int it = 0; it < NK; it++) {
        int s = it % NSTAGE;
        int pf = it + NSTAGE - 1;
        if (pf < NK) load_tiles(pf % NSTAGE, pf * 16);
        else cp_commit();                 // keep group count uniform
        cp_wait<NSTAGE - 1>();            // stage `it` ready
        __syncthreads();

        const float* As = sm + s * SS;
        const float* Bs = As + SA;
#pragma unroll
        for (int ks = 0; ks < 2; ks++) {
            unsigned a[MT][4], bf[NT][2];
#pragma unroll
            for (int mt = 0; mt < MT; mt++) {
                int r = wm * (16 * MT) + mt * 16 + g;
                int c = ks * 8 + t;
                float a0 = As[r * ASTRIDE + c];
                float a1 = As[(r + 8) * ASTRIDE + c];
                float a2 = As[r * ASTRIDE + c + 4];
                float a3 = As[(r + 8) * ASTRIDE + c + 4];
                if (ACVT) {
                    a[mt][0] = f2tf32(a0); a[mt][1] = f2tf32(a1);
                    a[mt][2] = f2tf32(a2); a[mt][3] = f2tf32(a3);
                } else {
                    a[mt][0] = __float_as_uint(a0); a[mt][1] = __float_as_uint(a1);
                    a[mt][2] = __float_as_uint(a2); a[mt][3] = __float_as_uint(a3);
                }
            }
#pragma unroll
            for (int nt = 0; nt < NT; nt++) {
                int n = wn * (8 * NT) + nt * 8 + g;
                int k = ks * 8 + t;
                bf[nt][0] = __float_as_uint(Bs[k * BSTRIDE + n]);
                bf[nt][1] = __float_as_uint(Bs[(k + 4) * BSTRIDE + n]);
            }
#pragma unroll
            for (int mt = 0; mt < MT; mt++)
#pragma unroll
                for (int nt = 0; nt < NT; nt++) mma_tf32(acc[mt][nt], a[mt], bf[nt]);
        }
        __syncthreads();
    }

    // epilogue
#pragma unroll
    for (int mt = 0; mt < MT; mt++) {
        int rbase = m0 + wm * (16 * MT) + mt * 16 + g;
#pragma unroll
        for (int half = 0; half < 2; half++) {
            int r = rbase + half * 8;
            if (r >= NN) continue;
            float sc = SCALE ? g_dinv[r] : 1.0f;
#pragma unroll
            for (int nt = 0; nt < NT; nt++) {
                int col = wn * (8 * NT) + nt * 8 + 2 * t;
                float v0 = acc[mt][nt][half * 2 + 0];
                float v1 = acc[mt][nt][half * 2 + 1];
                if (BIAS) { v0 += bias[col]; v1 += bias[col + 1]; }
                if (RELU) { v0 = fmaxf(v0, 0.0f); v1 = fmaxf(v1, 0.0f); }
                if (SCALE) { v0 *= sc; v1 *= sc; }
                if (OUTMODE == 2) {
                    ((__half2*)Cv)[(size_t)r * (NCOLS / 2) + (col >> 1)] =
                        __floats2half2_rn(v0, v1);
                } else {
                    if (OUTMODE == 1) { v0 = tf32round(v0); v1 = tf32round(v1); }
                    *(float2*)((float*)Cv + (size_t)r * NCOLS + col) = make_float2(v0, v1);
                }
            }
        }
    }
}

// dynamic smem sizes (bytes)
#define SMEM_PRE   (4 * (128 * ASTRIDE + 16 * (HDIM + 8)) * 4)   // 75776
#define SMEM_LAYER (3 * (128 * ASTRIDE + 16 * (HDIM + 8)) * 4)   // 56832
#define SMEM_MID   (3 * (128 * ASTRIDE + 16 * (MIDC + 8)) * 4)   // 69120

// gemm_pre: A = x (raw fp32 -> in-loop cvt), out g_h tf32-rounded. 128 thr, 4 stages.
__global__ __launch_bounds__(128) void gemm_pre_kernel(const float* __restrict__ x,
                                                       const float* __restrict__ bp) {
    gemm_tf32_body<DIN, HDIM, 2, 2, 4, true, true, true, false, 1>(x, g_wp_r, bp, g_h);
}

// layer GEMM: A = g_h (pre-rounded), out g_hw2 fp16 (scaled by dinv). 128 thr, 3 stages.
__global__ __launch_bounds__(128) void gemm_layer_kernel(int layer) {
    gemm_tf32_body<HDIM, HDIM, 2, 2, 3, false, false, false, true, 2>(
        g_h, g_wc_r + (size_t)layer * HDIM * HDIM, nullptr, g_hw2);
}

// heads hidden: A = g_h, B = g_w1cat, out g_mid fp32. 256 thr, 3 stages.
__global__ __launch_bounds__(256) void heads_mid_kernel() {
    gemm_tf32_body<HDIM, MIDC, 2, 4, 3, false, true, true, false, 0>(
        g_h, g_w1cat, g_b1cat, g_mid);
}

// ---------------- fused gather + self + bias + BN + relu + residual ----------
__device__ __forceinline__ void acc_hw(float4& a, const float2* row, int l) {
    float2 raw = row[l];
    __half2 h0 = *(__half2*)&raw.x;
    __half2 h1 = *(__half2*)&raw.y;
    float2 f0 = __half22float2(h0);
    float2 f1 = __half22float2(h1);
    a.x += f0.x; a.y += f0.y; a.z += f1.x; a.w += f1.y;
}

__global__ void gather_kernel(const float* __restrict__ bc_i,
                              const float* __restrict__ rmean,
                              const float* __restrict__ rvar,
                              const float* __restrict__ gamma,
                              const float* __restrict__ beta,
                              int residual) {
    int warp = (blockIdx.x * blockDim.x + threadIdx.x) >> 5;
    int l = threadIdx.x & 31;
    if (warp >= NN) return;
    const int n = warp;
    const int c0 = l * 4;

    const float2* hw = (const float2*)g_hw2;   // 32 float2 per row
    float4 acc0 = make_float4(0.f, 0.f, 0.f, 0.f);
    float4 acc1 = make_float4(0.f, 0.f, 0.f, 0.f);
    acc_hw(acc0, hw + (size_t)n * 32, l);      // self term (pre-scaled by dinv[n])

    int j = g_rowptr[n];
    const int end = g_rowptr[n + 1];
    for (; j + 8 <= end; j += 8) {
        int s0 = __ldg(&g_csr_src[j + 0]);
        int s1 = __ldg(&g_csr_src[j + 1]);
        int s2 = __ldg(&g_csr_src[j + 2]);
        int s3 = __ldg(&g_csr_src[j + 3]);
        int s4 = __ldg(&g_csr_src[j + 4]);
        int s5 = __ldg(&g_csr_src[j + 5]);
        int s6 = __ldg(&g_csr_src[j + 6]);
        int s7 = __ldg(&g_csr_src[j + 7]);
        acc_hw(acc0, hw + (size_t)s0 * 32, l);
        acc_hw(acc1, hw + (size_t)s1 * 32, l);
        acc_hw(acc0, hw + (size_t)s2 * 32, l);
        acc_hw(acc1, hw + (size_t)s3 * 32, l);
        acc_hw(acc0, hw + (size_t)s4 * 32, l);
        acc_hw(acc1, hw + (size_t)s5 * 32, l);
        acc_hw(acc0, hw + (size_t)s6 * 32, l);
        acc_hw(acc1, hw + (size_t)s7 * 32, l);
    }
    for (; j < end; j++) {
        int s = __ldg(&g_csr_src[j]);
        acc_hw(acc1, hw + (size_t)s * 32, l);
    }
    float4 acc = make_float4(acc0.x + acc1.x, acc0.y + acc1.y,
                             acc0.z + acc1.z, acc0.w + acc1.w);

    const float dn = g_dinv[n];
    float4 bc4 = *(const float4*)(bc_i + c0);
    float4 rm4 = *(const float4*)(rmean + c0);
    float4 rv4 = *(const float4*)(rvar + c0);
    float4 ga4 = *(const float4*)(gamma + c0);
    float4 be4 = *(const float4*)(beta + c0);

    float4 o;
    o.x = fmaxf((acc.x * dn + bc4.x - rm4.x) * rsqrtf(rv4.x + EPSBN) * ga4.x + be4.x, 0.0f);
    o.y = fmaxf((acc.y * dn + bc4.y - rm4.y) * rsqrtf(rv4.y + EPSBN) * ga4.y + be4.y, 0.0f);
    o.z = fmaxf((acc.z * dn + bc4.z - rm4.z) * rsqrtf(rv4.z + EPSBN) * ga4.z + be4.z, 0.0f);
    o.w = fmaxf((acc.w * dn + bc4.w - rm4.w) * rsqrtf(rv4.w + EPSBN) * ga4.w + be4.w, 0.0f);

    float4* h4 = (float4*)g_h;
    if (residual) {
        float4 hp = h4[(size_t)n * 32 + l];
        o.x += hp.x; o.y += hp.y; o.z += hp.z; o.w += hp.w;
    }
    // tf32-round so downstream GEMMs can consume raw bits (exact rna)
    o.x = tf32round(o.x); o.y = tf32round(o.y);
    o.z = tf32round(o.z); o.w = tf32round(o.w);
    h4[(size_t)n * 32 + l] = o;
}

// ---------------- heads second layer ------------------------------------------
// out layout: [0,N) risk_scores ; [N,5N) risk_logits [N,4] ; [5N,6N) relevance
__global__ void heads_out_kernel(const float* __restrict__ rs_W2, const float* __restrict__ rs_b2,
                                 const float* __restrict__ rl_W2, const float* __restrict__ rl_b2,
                                 const float* __restrict__ rel_W2, const float* __restrict__ rel_b2,
                                 float* __restrict__ out) {
    __shared__ float w_rs[HHALF];
    __shared__ float w_rl[HHALF * NRL];
    __shared__ float w_rel[HHALF];
    __shared__ float bsm[8];   // [0]=rs_b2, [1..4]=rl_b2, [5]=rel_b2

    const int tid = threadIdx.x;
    if (tid < HHALF) { w_rs[tid] = rs_W2[tid]; w_rel[tid] = rel_W2[tid]; }
    if (tid < HHALF * NRL) w_rl[tid] = rl_W2[tid];
    if (tid == 0) { bsm[0] = rs_b2[0]; bsm[5] = rel_b2[0]; }
    if (tid < NRL) bsm[1 + tid] = rl_b2[tid];
    __syncthreads();

    const int warp = (blockIdx.x * (blockDim.x >> 5)) + (tid >> 5);
    const int l = tid & 31;
    if (warp >= NN) return;
    const int n = warp;

    const float* m = g_mid + (size_t)n * MIDC;
    float m0 = m[l],        m1 = m[l + 32];
    float m2 = m[l + 64],   m3 = m[l + 96];
    float m4 = m[l + 128],  m5 = m[l + 160];

    float prs = m0 * w_rs[l] + m1 * w_rs[l + 32];
    float prel = m4 * w_rel[l] + m5 * w_rel[l + 32];
    float prl[NRL];
#pragma unroll
    for (int j = 0; j < NRL; j++)
        prl[j] = m2 * w_rl[l * NRL + j] + m3 * w_rl[(l + 32) * NRL + j];

#pragma unroll
    for (int o = 16; o; o >>= 1) {
        prs += __shfl_xor_sync(0xffffffffu, prs, o);
        prel += __shfl_xor_sync(0xffffffffu, prel, o);
#pragma unroll
        for (int j = 0; j < NRL; j++) prl[j] += __shfl_xor_sync(0xffffffffu, prl[j], o);
    }
    if (l == 0) {
        out[n] = 1.0f / (1.0f + expf(-(prs + bsm[0])));
#pragma unroll
        for (int j = 0; j < NRL; j++)
            out[(size_t)NN + (size_t)n * NRL + j] = prl[j] + bsm[1 + j];
        out[(size_t)5 * NN + n] = 1.0f / (1.0f + expf(-(prel + bsm[5])));
    }
}

// ---------------- launch ------------------------------------------------------
extern "C" void kernel_launch(void* const* d_in, const int* in_sizes, int n_in,
                              void* d_out, int out_size) {
    const float* x      = (const float*)d_in[0];
    const int*   ei     = (const int*)  d_in[1];
    const float* Wp     = (const float*)d_in[2];
    const float* bp     = (const float*)d_in[3];
    const float* Wc     = (const float*)d_in[4];
    const float* bc     = (const float*)d_in[5];
    const float* gamma  = (const float*)d_in[6];
    const float* beta   = (const float*)d_in[7];
    const float* rmean  = (const float*)d_in[8];
    const float* rvar   = (const float*)d_in[9];
    const float* rel_W1 = (const float*)d_in[10];
    const float* rel_b1 = (const float*)d_in[11];
    const float* rel_W2 = (const float*)d_in[12];
    const float* rel_b2 = (const float*)d_in[13];
    const float* rs_W1  = (const float*)d_in[14];
    const float* rs_b1  = (const float*)d_in[15];
    const float* rs_W2  = (const float*)d_in[16];
    const float* rs_b2  = (const float*)d_in[17];
    const float* rl_W1  = (const float*)d_in[18];
    const float* rl_b1  = (const float*)d_in[19];
    const float* rl_W2  = (const float*)d_in[20];
    const float* rl_b2  = (const float*)d_in[21];
    float* out = (float*)d_out;

    // raise dynamic smem limits (idempotent, capture-safe host calls)
    cudaFuncSetAttribute(gemm_pre_kernel, cudaFuncAttributeMaxDynamicSharedMemorySize, SMEM_PRE);
    cudaFuncSetAttribute(gemm_layer_kernel, cudaFuncAttributeMaxDynamicSharedMemorySize, SMEM_LAYER);
    cudaFuncSetAttribute(heads_mid_kernel, cudaFuncAttributeMaxDynamicSharedMemorySize, SMEM_MID);

    const int T = 256;
    const int gemm_blocks = (NN + 127) / 128;  // 782

    // fork-join: CSR build (stream sB) runs concurrently with weight prep +
    // gemm_pre (stream 0). Created per call, never destroyed (kernel_launch is
    // invoked only a handful of times; streams/events hold no tracked device mem).
    cudaStream_t sB;
    cudaStreamCreateWithFlags(&sB, cudaStreamNonBlocking);
    cudaEvent_t eFork, eJoin;
    cudaEventCreateWithFlags(&eFork, cudaEventDisableTiming);
    cudaEventCreateWithFlags(&eJoin, cudaEventDisableTiming);

    cudaEventRecord(eFork, 0);
    cudaStreamWaitEvent(sB, eFork, 0);

    // --- branch B: CSR build + heads weight concat ---
    deg_init_kernel<<<(NN + T - 1) / T, T, 0, sB>>>();
    deg_count_kernel<<<(EE + T - 1) / T, T, 0, sB>>>(ei);
    scan_partial_kernel<<<SCAN_NB, 512, 0, sB>>>();
    scan_bsum_kernel<<<1, 256, 0, sB>>>();
    scan_fill_kernel<<<SCAN_NB, 512, 0, sB>>>();
    csr_fill_kernel<<<(EE + T - 1) / T, T, 0, sB>>>(ei);
    w1cat_kernel<<<(HDIM * MIDC + T - 1) / T, T, 0, sB>>>(rs_W1, rs_b1, rl_W1, rl_b1,
                                                          rel_W1, rel_b1);
    cudaEventRecord(eJoin, sB);

    // --- branch A (origin stream): weight rounding + input projection ---
    round_weights_kernel<<<(DIN * HDIM + T - 1) / T, T>>>(Wp, Wc);
    gemm_pre_kernel<<<gemm_blocks, 128, SMEM_PRE>>>(x, bp);

    // join: layer loop needs CSR + dinv (branch B) and g_h (branch A)
    cudaStreamWaitEvent(0, eJoin, 0);

    const int gather_blocks = (NN * 32 + T - 1) / T;  // 12500
    for (int i = 0; i < NLAYERS; i++) {
        gemm_layer_kernel<<<gemm_blocks, 128, SMEM_LAYER>>>(i);
        gather_kernel<<<gather_blocks, T>>>(bc + (size_t)i * HDIM,
                                            rmean + (size_t)i * HDIM,
                                            rvar + (size_t)i * HDIM,
                                            gamma + (size_t)i * HDIM,
                                            beta + (size_t)i * HDIM,
                                            i > 0 ? 1 : 0);
    }

    heads_mid_kernel<<<gemm_blocks, 256, SMEM_MID>>>();
    heads_out_kernel<<<(NN * 32 + T - 1) / T, T>>>(rs_W2, rs_b2, rl_W2, rl_b2,
                                                   rel_W2, rel_b2, out);
}

// round 15
// speedup vs baseline: 1.4441x; 1.4441x over previous
#include <cuda_runtime.h>
#include <cuda_fp16.h>
#include <math.h>

#define NN 100000
#define EE 1600000
#define DIN 384
#define HDIM 128
#define HHALF 64
#define NLAYERS 3
#define NRL 4
#define EPSBN 1e-5f

#define SCAN_NB 200
#define SCAN_CHUNK 500

#define MIDC 192   // concatenated heads hidden width

// ---------------- scratch (device globals; no allocation allowed) ------------
__device__ float   g_h[NN * HDIM];       // current node features (tf32-rounded)
__device__ __half2 g_hw2[NN * HDIM / 2]; // (h @ Wc[i]) * dinv[row], fp16
__device__ float   g_mid[NN * MIDC];     // heads hidden
__device__ float   g_w1cat[HDIM * MIDC];
__device__ float   g_b1cat[MIDC];
__device__ float   g_wp_r[DIN * HDIM];            // tf32-rounded Wp
__device__ float   g_wc_r[NLAYERS * HDIM * HDIM]; // tf32-rounded Wc
__device__ float   g_dinv[NN];
__device__ int     g_cnt[NN];
__device__ int     g_rowptr[NN + 1];
__device__ int     g_csr_src[EE];
__device__ int     g_bsum[SCAN_NB];
__device__ int     g_boff[SCAN_NB];

__device__ __forceinline__ unsigned f2tf32(float x) {
    unsigned r;
    asm("cvt.rna.tf32.f32 %0, %1;" : "=r"(r) : "f"(x));
    return r;
}
__device__ __forceinline__ float tf32round(float x) {
    return __uint_as_float(f2tf32(x));
}

// ---------------- weight prep: tf32 pre-rounding -----------------------------
__global__ void round_weights_kernel(const float* __restrict__ Wp,
                                     const float* __restrict__ Wc) {
    int idx = blockIdx.x * blockDim.x + threadIdx.x;
    if (idx >= DIN * HDIM) return;
    g_wp_r[idx] = tf32round(Wp[idx]);
    g_wc_r[idx] = tf32round(Wc[idx]);
}

// ---------------- heads weight concat (tf32-rounded) --------------------------
__global__ void w1cat_kernel(const float* __restrict__ rs_W1, const float* __restrict__ rs_b1,
                             const float* __restrict__ rl_W1, const float* __restrict__ rl_b1,
                             const float* __restrict__ rel_W1, const float* __restrict__ rel_b1) {
    int idx = blockIdx.x * blockDim.x + threadIdx.x;   // [0, 128*192)
    if (idx >= HDIM * MIDC) return;
    int k = idx / MIDC, c = idx % MIDC;
    int head = c >> 6, j = c & 63;
    const float* W1 = (head == 0) ? rs_W1 : (head == 1) ? rl_W1 : rel_W1;
    g_w1cat[idx] = tf32round(W1[k * HHALF + j]);
    if (k == 0) {
        const float* B1 = (head == 0) ? rs_b1 : (head == 1) ? rl_b1 : rel_b1;
        g_b1cat[c] = B1[j];
    }
}

// ---------------- degree count ------------------------------------------------
__global__ void deg_init_kernel() {
    int i = blockIdx.x * blockDim.x + threadIdx.x;
    if (i < NN) g_cnt[i] = 0;
}

__global__ void deg_count_kernel(const int* __restrict__ ei) {
    int e = blockIdx.x * blockDim.x + threadIdx.x;
    if (e < EE) atomicAdd(&g_cnt[ei[EE + e]], 1);
}

// ---------------- 3-phase parallel scan --------------------------------------
__global__ void scan_partial_kernel() {   // grid SCAN_NB, block 512
    __shared__ int sh[512];
    int b = blockIdx.x, t = threadIdx.x;
    int i = b * SCAN_CHUNK + t;
    sh[t] = (t < SCAN_CHUNK) ? g_cnt[i] : 0;
    __syncthreads();
#pragma unroll
    for (int o = 256; o; o >>= 1) {
        if (t < o) sh[t] += sh[t + o];
        __syncthreads();
    }
    if (t == 0) g_bsum[b] = sh[0];
}

__global__ void scan_bsum_kernel() {      // 1 block, 256 threads
    __shared__ int sh[256];
    int t = threadIdx.x;
    sh[t] = (t < SCAN_NB) ? g_bsum[t] : 0;
    __syncthreads();
#pragma unroll
    for (int o = 1; o < 256; o <<= 1) {
        int v = (t >= o) ? sh[t - o] : 0;
        __syncthreads();
        sh[t] += v;
        __syncthreads();
    }
    if (t < SCAN_NB) g_boff[t] = (t ? sh[t - 1] : 0);
    if (t == 0) g_rowptr[NN] = EE;
}

__global__ void scan_fill_kernel() {      // grid SCAN_NB, block 512
    __shared__ int sh[512];
    int b = blockIdx.x, t = threadIdx.x;
    int i = b * SCAN_CHUNK + t;
    int c = (t < SCAN_CHUNK) ? g_cnt[i] : 0;
    sh[t] = c;
    __syncthreads();
#pragma unroll
    for (int o = 1; o < 512; o <<= 1) {
        int v = (t >= o) ? sh[t - o] : 0;
        __syncthreads();
        sh[t] += v;
        __syncthreads();
    }
    if (t < SCAN_CHUNK) {
        g_rowptr[i] = g_boff[b] + sh[t] - c;    // exclusive
        g_cnt[i] = 0;
        g_dinv[i] = rsqrtf((float)(c + 1));     // deg = in-degree + self loop
    }
}

__global__ void csr_fill_kernel(const int* __restrict__ ei) {
    int e = blockIdx.x * blockDim.x + threadIdx.x;
    if (e >= EE) return;
    int src = ei[e];
    int dst = ei[EE + e];
    int pos = g_rowptr[dst] + atomicAdd(&g_cnt[dst], 1);
    g_csr_src[pos] = src;
}

// ---------------- tf32 tensor-core GEMM v6 (multi-stage cp.async, param BM) ---
__device__ __forceinline__ void mma_tf32(float* c, const unsigned* a, const unsigned* b) {
    asm volatile(
        "mma.sync.aligned.m16n8k8.row.col.f32.tf32.tf32.f32 "
        "{%0,%1,%2,%3}, {%4,%5,%6,%7}, {%8,%9}, {%0,%1,%2,%3};"
        : "+f"(c[0]), "+f"(c[1]), "+f"(c[2]), "+f"(c[3])
        : "r"(a[0]), "r"(a[1]), "r"(a[2]), "r"(a[3]), "r"(b[0]), "r"(b[1]));
}

__device__ __forceinline__ void cp_async16(float* sdst, const float* gsrc, bool valid) {
    unsigned saddr = (unsigned)__cvta_generic_to_shared(sdst);
    int sz = valid ? 16 : 0;
    asm volatile("cp.async.cg.shared.global [%0], [%1], 16, %2;"
                 :: "r"(saddr), "l"(gsrc), "r"(sz));
}
__device__ __forceinline__ void cp_commit() { asm volatile("cp.async.commit_group;"); }
template <int N> __device__ __forceinline__ void cp_wait() {
    asm volatile("cp.async.wait_group %0;" :: "n"(N));
}

// C[M,NCOLS] = A[M,K] @ W[K,NCOLS] (+bias)(+relu)(*dinv[row]) -> f32/tf32/half2
// Block tile BM x NCOLS, BK=16. WM x WN warps; warp tile (BM/WM) x (NCOLS/WN).
#define ASTRIDE 20
template <int BM, int K, int NCOLS, int WM, int WN, int NSTAGE,
          bool ACVT, bool RELU, bool BIAS, bool SCALE, int OUTMODE>  // 0=f32,1=tf32,2=half2
__device__ __forceinline__ void gemm_tf32_body(const float* __restrict__ A,
                                               const float* __restrict__ W,
                                               const float* __restrict__ bias,
                                               void* __restrict__ Cv) {
    constexpr int THREADS = WM * WN * 32;
    constexpr int MT = BM / (16 * WM);
    constexpr int NT = NCOLS / (8 * WN);
    constexpr int BSTRIDE = NCOLS + 8;
    constexpr int NK = K / 16;
    constexpr int SA = BM * ASTRIDE;      // floats per A stage
    constexpr int SB = 16 * BSTRIDE;      // floats per B stage
    constexpr int SS = SA + SB;

    extern __shared__ float sm[];

    const int tid = threadIdx.x;
    const int wid = tid >> 5, lane = tid & 31;
    const int wm = wid % WM, wn = wid / WM;
    const int g = lane >> 2, t = lane & 3;
    const int m0 = blockIdx.x * BM;

    float acc[MT][NT][4];
#pragma unroll
    for (int mt = 0; mt < MT; mt++)
#pragma unroll
        for (int nt = 0; nt < NT; nt++)
#pragma unroll
            for (int i = 0; i < 4; i++) acc[mt][nt][i] = 0.0f;

    auto load_tiles = [&](int s, int k0) {
        float* As = sm + s * SS;
        float* Bs = As + SA;
#pragma unroll
        for (int idx = tid; idx < BM * 4; idx += THREADS) {  // A: BMx16 = BM*4 float4
            int r = idx >> 2, c4 = (idx & 3) * 4;
            int gr = m0 + r;
            bool v = (gr < NN);
            const float* src = A + (size_t)(v ? gr : 0) * K + k0 + c4;
            cp_async16(&As[r * ASTRIDE + c4], src, v);
        }
#pragma unroll
        for (int idx = tid; idx < 4 * NCOLS; idx += THREADS) {  // B: 16xNCOLS
            int kr = idx / (NCOLS / 4), c4 = (idx % (NCOLS / 4)) * 4;
            cp_async16(&Bs[kr * BSTRIDE + c4], W + (size_t)(k0 + kr) * NCOLS + c4, true);
        }
        cp_commit();
    };

#pragma unroll
    for (int p = 0; p < NSTAGE - 1; p++) load_tiles(p, p * 16);

    for (int it = 0; it < NK; it++) {
        int s = it % NSTAGE;
        int pf = it + NSTAGE - 1;
        if (pf < NK) load_tiles(pf % NSTAGE, pf * 16);
        else cp_commit();                 // keep group count uniform
        cp_wait<NSTAGE - 1>();            // stage `it` ready
        __syncthreads();

        const float* As = sm + s * SS;
        const float* Bs = As + SA;
#pragma unroll
        for (int ks = 0; ks < 2; ks++) {
            unsigned a[MT][4], bf[NT][2];
#pragma unroll
            for (int mt = 0; mt < MT; mt++) {
                int r = wm * (16 * MT) + mt * 16 + g;
                int c = ks * 8 + t;
                float a0 = As[r * ASTRIDE + c];
                float a1 = As[(r + 8) * ASTRIDE + c];
                float a2 = As[r * ASTRIDE + c + 4];
                float a3 = As[(r + 8) * ASTRIDE + c + 4];
                if (ACVT) {
                    a[mt][0] = f2tf32(a0); a[mt][1] = f2tf32(a1);
                    a[mt][2] = f2tf32(a2); a[mt][3] = f2tf32(a3);
                } else {
                    a[mt][0] = __float_as_uint(a0); a[mt][1] = __float_as_uint(a1);
                    a[mt][2] = __float_as_uint(a2); a[mt][3] = __float_as_uint(a3);
                }
            }
#pragma unroll
            for (int nt = 0; nt < NT; nt++) {
                int n = wn * (8 * NT) + nt * 8 + g;
                int k = ks * 8 + t;
                bf[nt][0] = __float_as_uint(Bs[k * BSTRIDE + n]);
                bf[nt][1] = __float_as_uint(Bs[(k + 4) * BSTRIDE + n]);
            }
#pragma unroll
            for (int mt = 0; mt < MT; mt++)
#pragma unroll
                for (int nt = 0; nt < NT; nt++) mma_tf32(acc[mt][nt], a[mt], bf[nt]);
        }
        __syncthreads();
    }

    // epilogue
#pragma unroll
    for (int mt = 0; mt < MT; mt++) {
        int rbase = m0 + wm * (16 * MT) + mt * 16 + g;
#pragma unroll
        for (int half = 0; half < 2; half++) {
            int r = rbase + half * 8;
            if (r >= NN) continue;
            float sc = SCALE ? g_dinv[r] : 1.0f;
#pragma unroll
            for (int nt = 0; nt < NT; nt++) {
                int col = wn * (8 * NT) + nt * 8 + 2 * t;
                float v0 = acc[mt][nt][half * 2 + 0];
                float v1 = acc[mt][nt][half * 2 + 1];
                if (BIAS) { v0 += bias[col]; v1 += bias[col + 1]; }
                if (RELU) { v0 = fmaxf(v0, 0.0f); v1 = fmaxf(v1, 0.0f); }
                if (SCALE) { v0 *= sc; v1 *= sc; }
                if (OUTMODE == 2) {
                    ((__half2*)Cv)[(size_t)r * (NCOLS / 2) + (col >> 1)] =
                        __floats2half2_rn(v0, v1);
                } else {
                    if (OUTMODE == 1) { v0 = tf32round(v0); v1 = tf32round(v1); }
                    *(float2*)((float*)Cv + (size_t)r * NCOLS + col) = make_float2(v0, v1);
                }
            }
        }
    }
}

// dynamic smem sizes (bytes)
#define SMEM_PRE   (4 * (64 * ASTRIDE + 16 * (HDIM + 8)) * 4)    // 55296 (BM=64, 4 stages)
#define SMEM_LAYER (3 * (128 * ASTRIDE + 16 * (HDIM + 8)) * 4)   // 56832
#define SMEM_MID   (3 * (128 * ASTRIDE + 16 * (MIDC + 8)) * 4)   // 69120

// gemm_pre: BM=64, 128 thr, 4 stages; A = x (raw fp32 -> in-loop cvt), out tf32-rounded.
__global__ __launch_bounds__(128) void gemm_pre_kernel(const float* __restrict__ x,
                                                       const float* __restrict__ bp) {
    gemm_tf32_body<64, DIN, HDIM, 2, 2, 4, true, true, true, false, 1>(x, g_wp_r, bp, g_h);
}

// layer GEMM: BM=128, 128 thr, 3 stages; out g_hw2 fp16 (scaled by dinv).
__global__ __launch_bounds__(128) void gemm_layer_kernel(int layer) {
    gemm_tf32_body<128, HDIM, HDIM, 2, 2, 3, false, false, false, true, 2>(
        g_h, g_wc_r + (size_t)layer * HDIM * HDIM, nullptr, g_hw2);
}

// heads hidden: BM=128, 256 thr, 3 stages; out g_mid fp32.
__global__ __launch_bounds__(256) void heads_mid_kernel() {
    gemm_tf32_body<128, HDIM, MIDC, 2, 4, 3, false, true, true, false, 0>(
        g_h, g_w1cat, g_b1cat, g_mid);
}

// ---------------- fused gather + self + bias + BN + relu + residual ----------
__device__ __forceinline__ void acc_hw(float4& a, const float2* row, int l) {
    float2 raw = row[l];
    __half2 h0 = *(__half2*)&raw.x;
    __half2 h1 = *(__half2*)&raw.y;
    float2 f0 = __half22float2(h0);
    float2 f1 = __half22float2(h1);
    a.x += f0.x; a.y += f0.y; a.z += f1.x; a.w += f1.y;
}

__global__ void gather_kernel(const float* __restrict__ bc_i,
                              const float* __restrict__ rmean,
                              const float* __restrict__ rvar,
                              const float* __restrict__ gamma,
                              const float* __restrict__ beta,
                              int residual) {
    int warp = (blockIdx.x * blockDim.x + threadIdx.x) >> 5;
    int l = threadIdx.x & 31;
    if (warp >= NN) return;
    const int n = warp;
    const int c0 = l * 4;

    const float2* hw = (const float2*)g_hw2;   // 32 float2 per row
    float4 acc0 = make_float4(0.f, 0.f, 0.f, 0.f);
    float4 acc1 = make_float4(0.f, 0.f, 0.f, 0.f);
    acc_hw(acc0, hw + (size_t)n * 32, l);      // self term (pre-scaled by dinv[n])

    int j = g_rowptr[n];
    const int end = g_rowptr[n + 1];
    for (; j + 8 <= end; j += 8) {
        int s0 = __ldg(&g_csr_src[j + 0]);
        int s1 = __ldg(&g_csr_src[j + 1]);
        int s2 = __ldg(&g_csr_src[j + 2]);
        int s3 = __ldg(&g_csr_src[j + 3]);
        int s4 = __ldg(&g_csr_src[j + 4]);
        int s5 = __ldg(&g_csr_src[j + 5]);
        int s6 = __ldg(&g_csr_src[j + 6]);
        int s7 = __ldg(&g_csr_src[j + 7]);
        acc_hw(acc0, hw + (size_t)s0 * 32, l);
        acc_hw(acc1, hw + (size_t)s1 * 32, l);
        acc_hw(acc0, hw + (size_t)s2 * 32, l);
        acc_hw(acc1, hw + (size_t)s3 * 32, l);
        acc_hw(acc0, hw + (size_t)s4 * 32, l);
        acc_hw(acc1, hw + (size_t)s5 * 32, l);
        acc_hw(acc0, hw + (size_t)s6 * 32, l);
        acc_hw(acc1, hw + (size_t)s7 * 32, l);
    }
    for (; j < end; j++) {
        int s = __ldg(&g_csr_src[j]);
        acc_hw(acc1, hw + (size_t)s * 32, l);
    }
    float4 acc = make_float4(acc0.x + acc1.x, acc0.y + acc1.y,
                             acc0.z + acc1.z, acc0.w + acc1.w);

    const float dn = g_dinv[n];
    float4 bc4 = *(const float4*)(bc_i + c0);
    float4 rm4 = *(const float4*)(rmean + c0);
    float4 rv4 = *(const float4*)(rvar + c0);
    float4 ga4 = *(const float4*)(gamma + c0);
    float4 be4 = *(const float4*)(beta + c0);

    float4 o;
    o.x = fmaxf((acc.x * dn + bc4.x - rm4.x) * rsqrtf(rv4.x + EPSBN) * ga4.x + be4.x, 0.0f);
    o.y = fmaxf((acc.y * dn + bc4.y - rm4.y) * rsqrtf(rv4.y + EPSBN) * ga4.y + be4.y, 0.0f);
    o.z = fmaxf((acc.z * dn + bc4.z - rm4.z) * rsqrtf(rv4.z + EPSBN) * ga4.z + be4.z, 0.0f);
    o.w = fmaxf((acc.w * dn + bc4.w - rm4.w) * rsqrtf(rv4.w + EPSBN) * ga4.w + be4.w, 0.0f);

    float4* h4 = (float4*)g_h;
    if (residual) {
        float4 hp = h4[(size_t)n * 32 + l];
        o.x += hp.x; o.y += hp.y; o.z += hp.z; o.w += hp.w;
    }
    // tf32-round so downstream GEMMs can consume raw bits (exact rna)
    o.x = tf32round(o.x); o.y = tf32round(o.y);
    o.z = tf32round(o.z); o.w = tf32round(o.w);
    h4[(size_t)n * 32 + l] = o;
}

// ---------------- heads second layer ------------------------------------------
// out layout: [0,N) risk_scores ; [N,5N) risk_logits [N,4] ; [5N,6N) relevance
__global__ void heads_out_kernel(const float* __restrict__ rs_W2, const float* __restrict__ rs_b2,
                                 const float* __restrict__ rl_W2, const float* __restrict__ rl_b2,
                                 const float* __restrict__ rel_W2, const float* __restrict__ rel_b2,
                                 float* __restrict__ out) {
    __shared__ float w_rs[HHALF];
    __shared__ float w_rl[HHALF * NRL];
    __shared__ float w_rel[HHALF];
    __shared__ float bsm[8];   // [0]=rs_b2, [1..4]=rl_b2, [5]=rel_b2

    const int tid = threadIdx.x;
    if (tid < HHALF) { w_rs[tid] = rs_W2[tid]; w_rel[tid] = rel_W2[tid]; }
    if (tid < HHALF * NRL) w_rl[tid] = rl_W2[tid];
    if (tid == 0) { bsm[0] = rs_b2[0]; bsm[5] = rel_b2[0]; }
    if (tid < NRL) bsm[1 + tid] = rl_b2[tid];
    __syncthreads();

    const int warp = (blockIdx.x * (blockDim.x >> 5)) + (tid >> 5);
    const int l = tid & 31;
    if (warp >= NN) return;
    const int n = warp;

    const float* m = g_mid + (size_t)n * MIDC;
    float m0 = m[l],        m1 = m[l + 32];
    float m2 = m[l + 64],   m3 = m[l + 96];
    float m4 = m[l + 128],  m5 = m[l + 160];

    float prs = m0 * w_rs[l] + m1 * w_rs[l + 32];
    float prel = m4 * w_rel[l] + m5 * w_rel[l + 32];
    float prl[NRL];
#pragma unroll
    for (int j = 0; j < NRL; j++)
        prl[j] = m2 * w_rl[l * NRL + j] + m3 * w_rl[(l + 32) * NRL + j];

#pragma unroll
    for (int o = 16; o; o >>= 1) {
        prs += __shfl_xor_sync(0xffffffffu, prs, o);
        prel += __shfl_xor_sync(0xffffffffu, prel, o);
#pragma unroll
        for (int j = 0; j < NRL; j++) prl[j] += __shfl_xor_sync(0xffffffffu, prl[j], o);
    }
    if (l == 0) {
        out[n] = 1.0f / (1.0f + expf(-(prs + bsm[0])));
#pragma unroll
        for (int j = 0; j < NRL; j++)
            out[(size_t)NN + (size_t)n * NRL + j] = prl[j] + bsm[1 + j];
        out[(size_t)5 * NN + n] = 1.0f / (1.0f + expf(-(prel + bsm[5])));
    }
}

// ---------------- launch ------------------------------------------------------
extern "C" void kernel_launch(void* const* d_in, const int* in_sizes, int n_in,
                              void* d_out, int out_size) {
    const float* x      = (const float*)d_in[0];
    const int*   ei     = (const int*)  d_in[1];
    const float* Wp     = (const float*)d_in[2];
    const float* bp     = (const float*)d_in[3];
    const float* Wc     = (const float*)d_in[4];
    const float* bc     = (const float*)d_in[5];
    const float* gamma  = (const float*)d_in[6];
    const float* beta   = (const float*)d_in[7];
    const float* rmean  = (const float*)d_in[8];
    const float* rvar   = (const float*)d_in[9];
    const float* rel_W1 = (const float*)d_in[10];
    const float* rel_b1 = (const float*)d_in[11];
    const float* rel_W2 = (const float*)d_in[12];
    const float* rel_b2 = (const float*)d_in[13];
    const float* rs_W1  = (const float*)d_in[14];
    const float* rs_b1  = (const float*)d_in[15];
    const float* rs_W2  = (const float*)d_in[16];
    const float* rs_b2  = (const float*)d_in[17];
    const float* rl_W1  = (const float*)d_in[18];
    const float* rl_b1  = (const float*)d_in[19];
    const float* rl_W2  = (const float*)d_in[20];
    const float* rl_b2  = (const float*)d_in[21];
    float* out = (float*)d_out;

    // raise dynamic smem limits (idempotent, capture-safe host calls)
    cudaFuncSetAttribute(gemm_pre_kernel, cudaFuncAttributeMaxDynamicSharedMemorySize, SMEM_PRE);
    cudaFuncSetAttribute(gemm_layer_kernel, cudaFuncAttributeMaxDynamicSharedMemorySize, SMEM_LAYER);
    cudaFuncSetAttribute(heads_mid_kernel, cudaFuncAttributeMaxDynamicSharedMemorySize, SMEM_MID);

    const int T = 256;
    const int gemm_blocks = (NN + 127) / 128;      // 782
    const int pre_blocks = (NN + 63) / 64;         // 1563

    // launches 1-3: prep; launch 4 = gemm_pre (profiled slot)
    deg_init_kernel<<<(NN + T - 1) / T, T>>>();
    deg_count_kernel<<<(EE + T - 1) / T, T>>>(ei);
    round_weights_kernel<<<(DIN * HDIM + T - 1) / T, T>>>(Wp, Wc);
    gemm_pre_kernel<<<pre_blocks, 128, SMEM_PRE>>>(x, bp);

    scan_partial_kernel<<<SCAN_NB, 512>>>();
    scan_bsum_kernel<<<1, 256>>>();
    scan_fill_kernel<<<SCAN_NB, 512>>>();
    csr_fill_kernel<<<(EE + T - 1) / T, T>>>(ei);
    w1cat_kernel<<<(HDIM * MIDC + T - 1) / T, T>>>(rs_W1, rs_b1, rl_W1, rl_b1, rel_W1, rel_b1);

    const int gather_blocks = (NN * 32 + T - 1) / T;  // 12500
    for (int i = 0; i < NLAYERS; i++) {
        gemm_layer_kernel<<<gemm_blocks, 128, SMEM_LAYER>>>(i);
        gather_kernel<<<gather_blocks, T>>>(bc + (size_t)i * HDIM,
                                            rmean + (size_t)i * HDIM,
                                            rvar + (size_t)i * HDIM,
                                            gamma + (size_t)i * HDIM,
                                            beta + (size_t)i * HDIM,
                                            i > 0 ? 1 : 0);
    }

    heads_mid_kernel<<<gemm_blocks, 256, SMEM_MID>>>();
    heads_out_kernel<<<(NN * 32 + T - 1) / T, T>>>(rs_W2, rs_b2, rl_W2, rl_b2,
                                                   rel_W2, rel_b2, out);
}